// round 15
// baseline (speedup 1.0000x reference)
#include <cuda_runtime.h>
#include <cuda_bf16.h>
#include <cuda_fp16.h>
#include <cstdint>

#define NN 20000    // nodes
#define D  128      // dim
#define NE 200000   // edges
#define NT 8        // timesteps
#define NRP 20096   // padded rows (157*128)
#define NTIL64 314  // 64-row tiles (NRP/64)
#define NTT (NT * NTIL64)   // 2512 (t,tile) pairs for enc_gates
#define NTIL32 625  // 32-row tiles for step_all (exact: 625*32 = 20000)
#define PAD 136     // bf16 elems per padded smem row (step_all layout)

// ---- static device scratch (no runtime allocation) ----
__device__ float  g_agg[(size_t)NT * NRP * D];  // per-time aggregated messages
__device__ uint4  g_Wp[5 * 2 * 128 * 16];       // 5 weights x {hi,lo} x [n][k] bf16 linear
__device__ __half g_GZ[(size_t)NT * NRP * D];   // H@Wz (fp16 preact)
__device__ __half g_GH[(size_t)NT * NRP * D];   // H@Wh

// ---- enc_gates smem (XOR-swizzled 256B rows; weight splits are 32KB each) ----
#define EX_HI 0
#define EX_LO 16384
#define EWE_HI 32768
#define EWE_LO 65536
#define EWZ_HI 98304
#define EWZ_LO 131072
#define EWH_HI 163840
#define EWH_LO 196608
#define SMEM_ENC 229376

// ---- step_all smem: Uz + Uh (padded rows) + per-group DOUBLE SX buffers ----
#define SW0_HI 0
#define SW0_LO 34816
#define SW1_HI 69632
#define SW1_LO 104448
#define SXBASE 139264
#define SXG 17408            // one SX buffer (hi 8704 + lo 8704)
#define SMEM_STEP (SXBASE + 4 * SXG)   // 208896: 2 groups x 2 tiles

// ---------------------------------------------------------------------------
__device__ __forceinline__ uint32_t smem_u32(const void* p) {
    uint32_t a;
    asm("{ .reg .u64 t; cvta.to.shared.u64 t, %1; cvt.u32.u64 %0, t; }" : "=r"(a) : "l"(p));
    return a;
}

#define LDSM4(R, a) \
    asm volatile("ldmatrix.sync.aligned.m8n8.x4.shared.b16 {%0,%1,%2,%3}, [%4];" \
                 : "=r"((R)[0]), "=r"((R)[1]), "=r"((R)[2]), "=r"((R)[3]) : "r"(a))

#define MMA16816(d, a, b0, b1) \
    asm volatile("mma.sync.aligned.m16n8k16.row.col.f32.bf16.bf16.f32 " \
                 "{%0,%1,%2,%3},{%4,%5,%6,%7},{%8,%9},{%0,%1,%2,%3};" \
                 : "+f"((d)[0]), "+f"((d)[1]), "+f"((d)[2]), "+f"((d)[3]) \
                 : "r"((a)[0]), "r"((a)[1]), "r"((a)[2]), "r"((a)[3]), "r"(b0), "r"(b1))

#define BARH(id) asm volatile("bar.sync %0, 128;" :: "r"(id) : "memory")

__device__ __forceinline__ void split2(float x, float y, uint32_t& h, uint32_t& l) {
    __nv_bfloat16 hx = __float2bfloat16(x), hy = __float2bfloat16(y);
    float rx = x - __bfloat162float(hx);
    float ry = y - __bfloat162float(hy);
    __nv_bfloat16 lx = __float2bfloat16(rx), ly = __float2bfloat16(ry);
    h = (uint32_t)__bfloat16_as_ushort(hx) | ((uint32_t)__bfloat16_as_ushort(hy) << 16);
    l = (uint32_t)__bfloat16_as_ushort(lx) | ((uint32_t)__bfloat16_as_ushort(ly) << 16);
}

// Fast MUFU-based transcendentals (rel err ~1e-6; inf-safe saturation)
__device__ __forceinline__ float fsig(float x) {
    return __fdividef(1.f, 1.f + __expf(-x));
}
__device__ __forceinline__ float ftanh(float x) {
    return 1.f - __fdividef(2.f, __expf(2.f * x) + 1.f);
}

// ---------------------------------------------------------------------------
__global__ void prep_weights(const float* W0, const float* W1, const float* W2,
                             const float* W3, const float* W4) {
    int idx = blockIdx.x * blockDim.x + threadIdx.x;
    if (idx >= 5 * 128 * 128) return;
    int w = idx >> 14, rem = idx & 16383, n = rem >> 7, k = rem & 127;
    const float* Ws = (w == 0) ? W0 : (w == 1) ? W1 : (w == 2) ? W2 : (w == 3) ? W3 : W4;
    float v = Ws[k * 128 + n];
    __nv_bfloat16 hv = __float2bfloat16(v);
    float res = v - __bfloat162float(hv);
    __nv_bfloat16 lv = __float2bfloat16(res);
    unsigned short* base = (unsigned short*)g_Wp;
    base[(size_t)((w * 2 + 0) * 128 + n) * 128 + k] = __bfloat16_as_ushort(hv);
    base[(size_t)((w * 2 + 1) * 128 + n) * 128 + k] = __bfloat16_as_ushort(lv);
}

__global__ void scatter_kernel(const int* __restrict__ src, const int* __restrict__ dst,
                               const int* __restrict__ etype, const int* __restrict__ etime,
                               const float* __restrict__ ew,
                               const float* __restrict__ node_emb,
                               const float* __restrict__ rel_emb) {
    int gid  = blockIdx.x * blockDim.x + threadIdx.x;
    int e    = gid >> 5;
    int lane = gid & 31;
    if (e >= NE) return;
    int t = etime[e];
    if ((unsigned)t >= NT) return;
    int s = src[e], d = dst[e], r = etype[e];
    float w = ew[e];
    float4 a = reinterpret_cast<const float4*>(node_emb + (size_t)s * D)[lane];
    float4 b = reinterpret_cast<const float4*>(rel_emb  + (size_t)r * D)[lane];
    float* o = g_agg + ((size_t)t * NRP + d) * D + lane * 4;
    asm volatile("red.global.add.v4.f32 [%0], {%1,%2,%3,%4};"
                 :: "l"(o), "f"(a.x * b.x * w), "f"(a.y * b.y * w),
                    "f"(a.z * b.z * w), "f"(a.w * b.w * w) : "memory");
}

// ---------------------------------------------------------------------------
// enc_gates (unchanged): fused H = tanh(agg@Wenc) smem-only, then dual GZ/GH
// GEMM sharing H fragments. 64-row tiles, 512 thr. fp16 outputs.
// ---------------------------------------------------------------------------
__device__ __forceinline__ void copy_w_swz(char* sm_, int w, int tid,
                                           int hi_off, int lo_off) {
    const uint4* s = g_Wp + (size_t)w * 4096;
    for (int i = tid; i < 4096; i += 512) {
        int sp = i >> 11, j = i & 2047, n = j >> 4, c = j & 15;
        uint32_t off = (uint32_t)(n * 256) + (((c ^ (n & 7)) & 15) << 4);
        *(uint4*)(sm_ + (sp ? lo_off : hi_off) + off) = s[i];
    }
}

__device__ __forceinline__ void gemm64sw(float (&acc)[2][2][4],
                                         uint32_t xhi, uint32_t xlo,
                                         uint32_t whi, uint32_t wlo,
                                         int lane, int wm, int wn) {
    int ar = wm * 32 + (lane & 15);
    int ach = lane >> 4;
    int brow = wn * 16 + (lane & 7) + ((lane >> 4) & 1) * 8;
    int bch = (lane >> 3) & 1;
    uint32_t ab0 = (uint32_t)(ar * 256), ab1 = (uint32_t)((ar + 16) * 256);
    int am = ar & 7;
    uint32_t bb = (uint32_t)(brow * 256);
    int bm = brow & 7;
#pragma unroll 2
    for (int ks = 0; ks < 8; ks++) {
        uint32_t Ah[2][4], Al[2][4], Bh[4], Bl[4];
        uint32_t ao = (uint32_t)((((ks * 2 + ach) ^ am) & 15) << 4);
        uint32_t bo = (uint32_t)((((ks * 2 + bch) ^ bm) & 15) << 4);
        LDSM4(Ah[0], xhi + ab0 + ao);
        LDSM4(Al[0], xlo + ab0 + ao);
        LDSM4(Ah[1], xhi + ab1 + ao);
        LDSM4(Al[1], xlo + ab1 + ao);
        LDSM4(Bh, whi + bb + bo);
        LDSM4(Bl, wlo + bb + bo);
#pragma unroll
        for (int tm = 0; tm < 2; tm++)
#pragma unroll
            for (int tn = 0; tn < 2; tn++) {
                int o = tn * 2;
                MMA16816(acc[tm][tn], Ah[tm], Bh[o], Bh[o + 1]);
                MMA16816(acc[tm][tn], Al[tm], Bh[o], Bh[o + 1]);
                MMA16816(acc[tm][tn], Ah[tm], Bl[o], Bl[o + 1]);
            }
    }
}

__device__ __forceinline__ void gemm64sw_dual(float (&aZ)[2][2][4], float (&aH)[2][2][4],
                                              uint32_t xhi, uint32_t xlo,
                                              uint32_t zhi, uint32_t zlo,
                                              uint32_t hhi, uint32_t hlo,
                                              int lane, int wm, int wn) {
    int ar = wm * 32 + (lane & 15);
    int ach = lane >> 4;
    int brow = wn * 16 + (lane & 7) + ((lane >> 4) & 1) * 8;
    int bch = (lane >> 3) & 1;
    uint32_t ab0 = (uint32_t)(ar * 256), ab1 = (uint32_t)((ar + 16) * 256);
    int am = ar & 7;
    uint32_t bb = (uint32_t)(brow * 256);
    int bm = brow & 7;
#pragma unroll 1
    for (int ks = 0; ks < 8; ks++) {
        uint32_t Ah[2][4], Al[2][4], Bzh[4], Bzl[4], Bhh[4], Bhl[4];
        uint32_t ao = (uint32_t)((((ks * 2 + ach) ^ am) & 15) << 4);
        uint32_t bo = (uint32_t)((((ks * 2 + bch) ^ bm) & 15) << 4);
        LDSM4(Ah[0], xhi + ab0 + ao);
        LDSM4(Al[0], xlo + ab0 + ao);
        LDSM4(Ah[1], xhi + ab1 + ao);
        LDSM4(Al[1], xlo + ab1 + ao);
        LDSM4(Bzh, zhi + bb + bo);
        LDSM4(Bzl, zlo + bb + bo);
        LDSM4(Bhh, hhi + bb + bo);
        LDSM4(Bhl, hlo + bb + bo);
#pragma unroll
        for (int tm = 0; tm < 2; tm++)
#pragma unroll
            for (int tn = 0; tn < 2; tn++) {
                int o = tn * 2;
                MMA16816(aZ[tm][tn], Ah[tm], Bzh[o], Bzh[o + 1]);
                MMA16816(aZ[tm][tn], Al[tm], Bzh[o], Bzh[o + 1]);
                MMA16816(aZ[tm][tn], Ah[tm], Bzl[o], Bzl[o + 1]);
                MMA16816(aH[tm][tn], Ah[tm], Bhh[o], Bhh[o + 1]);
                MMA16816(aH[tm][tn], Al[tm], Bhh[o], Bhh[o + 1]);
                MMA16816(aH[tm][tn], Ah[tm], Bhl[o], Bhl[o + 1]);
            }
    }
}

#define ZERO_ACC224(acc) \
    { _Pragma("unroll") for (int i = 0; i < 2; i++) \
      _Pragma("unroll") for (int j = 0; j < 2; j++) \
      _Pragma("unroll") for (int q = 0; q < 4; q++) (acc)[i][j][q] = 0.f; }

__global__ void __launch_bounds__(512, 1) enc_gates() {
    extern __shared__ char sm[];
    uint32_t sb = smem_u32(sm);
    int tid = threadIdx.x, lane = tid & 31, wid = tid >> 5;
    int wm = wid & 1, wn = wid >> 1;

    copy_w_swz(sm, 0, tid, EWE_HI, EWE_LO);
    copy_w_swz(sm, 1, tid, EWZ_HI, EWZ_LO);
    copy_w_swz(sm, 3, tid, EWH_HI, EWH_LO);

    int xrow = tid >> 3, xseg = (tid & 7) * 16;
    int xc0 = xseg >> 3;

    float4 pf[4];
    {
        int tt = blockIdx.x;
        int t = tt / NTIL64, tile = tt - t * NTIL64;
        const float4* s = (const float4*)(g_agg + ((size_t)t * NRP + tile * 64 + xrow) * D + xseg);
#pragma unroll
        for (int q = 0; q < 4; q++) pf[q] = s[q];
    }

    for (int tt = blockIdx.x; tt < NTT; tt += gridDim.x) {
        int t = tt / NTIL64, tile = tt - t * NTIL64;

        __syncthreads();
#pragma unroll
        for (int g = 0; g < 2; g++) {
            float4 a = pf[g * 2], b = pf[g * 2 + 1];
            uint32_t h0, h1, h2, h3, l0, l1, l2, l3;
            split2(a.x, a.y, h0, l0);
            split2(a.z, a.w, h1, l1);
            split2(b.x, b.y, h2, l2);
            split2(b.z, b.w, h3, l3);
            uint32_t off = (uint32_t)(xrow * 256) + ((((xc0 + g) ^ (xrow & 7)) & 15) << 4);
            *(uint4*)(sm + EX_HI + off) = make_uint4(h0, h1, h2, h3);
            *(uint4*)(sm + EX_LO + off) = make_uint4(l0, l1, l2, l3);
        }
        __syncthreads();

        float acc[2][2][4];
        ZERO_ACC224(acc);
        gemm64sw(acc, sb + EX_HI, sb + EX_LO, sb + EWE_HI, sb + EWE_LO, lane, wm, wn);
        __syncthreads();

#pragma unroll
        for (int tm = 0; tm < 2; tm++)
#pragma unroll
            for (int tn = 0; tn < 2; tn++) {
                int c = wn * 16 + tn * 8 + (lane & 3) * 2;
#pragma unroll
                for (int h2i = 0; h2i < 2; h2i++) {
                    int r = wm * 32 + tm * 16 + (lane >> 2) + h2i * 8;
                    uint32_t h, l;
                    split2(ftanh(acc[tm][tn][h2i * 2]), ftanh(acc[tm][tn][h2i * 2 + 1]), h, l);
                    uint32_t off = (uint32_t)(r * 256) + ((((c >> 3) ^ (r & 7)) & 15) << 4)
                                 + (uint32_t)((c & 7) * 2);
                    *(uint32_t*)(sm + EX_HI + off) = h;
                    *(uint32_t*)(sm + EX_LO + off) = l;
                }
            }
        __syncthreads();

        if (tt + (int)gridDim.x < NTT) {
            int nt2 = tt + gridDim.x;
            int t2 = nt2 / NTIL64, tile2 = nt2 - t2 * NTIL64;
            const float4* s = (const float4*)(g_agg + ((size_t)t2 * NRP + tile2 * 64 + xrow) * D + xseg);
#pragma unroll
            for (int q = 0; q < 4; q++) pf[q] = s[q];
        }

        float accZ[2][2][4], accH[2][2][4];
        ZERO_ACC224(accZ);
        ZERO_ACC224(accH);
        gemm64sw_dual(accZ, accH, sb + EX_HI, sb + EX_LO,
                      sb + EWZ_HI, sb + EWZ_LO, sb + EWH_HI, sb + EWH_LO, lane, wm, wn);

        size_t base = (size_t)t * NRP + (size_t)tile * 64;
#pragma unroll
        for (int tm = 0; tm < 2; tm++)
#pragma unroll
            for (int tn = 0; tn < 2; tn++) {
                int c = wn * 16 + tn * 8 + (lane & 3) * 2;
#pragma unroll
                for (int h2i = 0; h2i < 2; h2i++) {
                    int r = wm * 32 + tm * 16 + (lane >> 2) + h2i * 8;
                    __half2 hz = __floats2half2_rn(accZ[tm][tn][h2i * 2], accZ[tm][tn][h2i * 2 + 1]);
                    __half2 hh = __floats2half2_rn(accH[tm][tn][h2i * 2], accH[tm][tn][h2i * 2 + 1]);
                    *(__half2*)(g_GZ + (base + r) * D + c) = hz;
                    *(__half2*)(g_GH + (base + r) * D + c) = hh;
                }
            }
    }
}

// ---------------------------------------------------------------------------
// step_all: 2 groups/CTA x 2 wm-halves = 4 sync domains; each group runs TWO
// independent 32-row tiles (A,B) through the recurrence per iteration —
// splitA/splitB share one barrier, gemmB+gruB overlap gemmA/gruA latency.
// ---------------------------------------------------------------------------
__device__ __forceinline__ void copy_w_pad(char* sm_, int w, int tid,
                                           int hi_off, int lo_off) {
    const uint4* s = g_Wp + (size_t)w * 4096;
    for (int i = tid; i < 4096; i += 512) {
        int sp = i >> 11, j = i & 2047, n = j >> 4, kk = j & 15;
        *(uint4*)(sm_ + (sp ? lo_off : hi_off) + (uint32_t)(n * PAD + kk * 8) * 2) = s[i];
    }
}

__device__ __forceinline__ void gemm_step_dual(float (&aZ)[4][4], float (&aH)[4][4],
                                               uint32_t xhi, uint32_t xlo,
                                               uint32_t zhi, uint32_t zlo,
                                               uint32_t hhi, uint32_t hlo,
                                               int lane, int wm, int wn) {
    const int arow = wm * 16 + (lane & 15);
    const int acolo = (lane >> 4) * 8;
    const int brow = wn * 32 + (lane & 7) + ((lane >> 4) & 1) * 8;
    const int bcolo = ((lane >> 3) & 1) * 8;
    const uint32_t bstep = (uint32_t)(16 * PAD) * 2;
#pragma unroll 1
    for (int ks = 0; ks < 8; ks++) {
        uint32_t Ah[4], Al[4], Bzh[8], Bzl[8], Bhh[8], Bhl[8];
        uint32_t ao = (uint32_t)(arow * PAD + ks * 16 + acolo) * 2;
        uint32_t bo = (uint32_t)(brow * PAD + ks * 16 + bcolo) * 2;
        LDSM4(Ah, xhi + ao);
        LDSM4(Al, xlo + ao);
        LDSM4(Bzh, zhi + bo);
        LDSM4(Bzh + 4, zhi + bo + bstep);
        LDSM4(Bzl, zlo + bo);
        LDSM4(Bzl + 4, zlo + bo + bstep);
        LDSM4(Bhh, hhi + bo);
        LDSM4(Bhh + 4, hhi + bo + bstep);
        LDSM4(Bhl, hlo + bo);
        LDSM4(Bhl + 4, hlo + bo + bstep);
#pragma unroll
        for (int tn = 0; tn < 4; tn++) {
            int o = tn * 2;
            MMA16816(aZ[tn], Ah, Bzh[o], Bzh[o + 1]);
            MMA16816(aZ[tn], Al, Bzh[o], Bzh[o + 1]);
            MMA16816(aZ[tn], Ah, Bzl[o], Bzl[o + 1]);
            MMA16816(aH[tn], Ah, Bhh[o], Bhh[o + 1]);
            MMA16816(aH[tn], Al, Bhh[o], Bhh[o + 1]);
            MMA16816(aH[tn], Ah, Bhl[o], Bhl[o + 1]);
        }
    }
}

__global__ void __launch_bounds__(512, 1) step_all(const float* __restrict__ bz,
                                                   const float* __restrict__ bh,
                                                   float* __restrict__ out) {
    extern __shared__ char sm[];
    uint32_t sb = smem_u32(sm);
    int tid = threadIdx.x, lane = tid & 31, wid = tid >> 5;
    int grp = wid >> 3;
    int lw = wid & 7;
    int wm = lw & 1, wn = lw >> 1;
    int barid = 1 + grp * 2 + wm;

    copy_w_pad(sm, 2, tid, SW0_HI, SW0_LO);  // Uz
    copy_w_pad(sm, 4, tid, SW1_HI, SW1_LO);  // Uh

    char* sxA = sm + SXBASE + (grp * 2) * SXG;
    char* sxB = sxA + SXG;
    uint32_t sxAhi = sb + SXBASE + (grp * 2) * SXG, sxAlo = sxAhi + 8704;
    uint32_t sxBhi = sxAhi + SXG, sxBlo = sxBhi + 8704;

    int cols[4];
#pragma unroll
    for (int tn = 0; tn < 4; tn++) cols[tn] = wn * 32 + tn * 8 + (lane & 3) * 2;
    int rowsl[2];
#pragma unroll
    for (int h2 = 0; h2 < 2; h2++) rowsl[h2] = wm * 16 + (lane >> 2) + h2 * 8;

    float2 bzv[4], bhv[4];
#pragma unroll
    for (int tn = 0; tn < 4; tn++) {
        bzv[tn] = *(const float2*)(bz + cols[tn]);
        bhv[tn] = *(const float2*)(bh + cols[tn]);
    }
    __syncthreads();  // weights ready (only full-CTA barrier)

    for (int base2 = blockIdx.x * 4 + grp * 2; base2 < NTIL32; base2 += 592) {
        int tileA = base2;
        int tileB = base2 + 1;
        bool vB = tileB < NTIL32;
        int tileBc = vB ? tileB : tileA;   // clamped for safe loads

        float SA[4][4], SB[4][4];
#pragma unroll
        for (int tn = 0; tn < 4; tn++)
#pragma unroll
            for (int q = 0; q < 4; q++) { SA[tn][q] = 0.f; SB[tn][q] = 0.f; }

        for (int t = 0; t < NT; t++) {
            size_t baseA = (size_t)t * NRP + (size_t)tileA * 32;
            size_t baseB = (size_t)t * NRP + (size_t)tileBc * 32;

            // early-issue tile A's gz/gh
            float2 gzA[4][2], ghA[4][2];
#pragma unroll
            for (int tn = 0; tn < 4; tn++)
#pragma unroll
                for (int h2 = 0; h2 < 2; h2++) {
                    size_t idx = (baseA + rowsl[h2]) * D + cols[tn];
                    gzA[tn][h2] = __half22float2(*(const __half2*)(g_GZ + idx));
                    ghA[tn][h2] = __half22float2(*(const __half2*)(g_GH + idx));
                }

            float aZ[4][4], aH[4][4];
#pragma unroll
            for (int tn = 0; tn < 4; tn++)
#pragma unroll
                for (int q = 0; q < 4; q++) { aZ[tn][q] = 0.f; aH[tn][q] = 0.f; }

            if (t > 0) {
                // split both tiles' states, one barrier
#pragma unroll
                for (int tn = 0; tn < 4; tn++)
#pragma unroll
                    for (int h2 = 0; h2 < 2; h2++) {
                        uint32_t off = (uint32_t)(rowsl[h2] * PAD + cols[tn]) * 2;
                        uint32_t h, l;
                        split2(SA[tn][h2 * 2], SA[tn][h2 * 2 + 1], h, l);
                        *(uint32_t*)(sxA + off) = h;
                        *(uint32_t*)(sxA + 8704 + off) = l;
                        split2(SB[tn][h2 * 2], SB[tn][h2 * 2 + 1], h, l);
                        *(uint32_t*)(sxB + off) = h;
                        *(uint32_t*)(sxB + 8704 + off) = l;
                    }
                BARH(barid);
                gemm_step_dual(aZ, aH, sxAhi, sxAlo,
                               sb + SW0_HI, sb + SW0_LO, sb + SW1_HI, sb + SW1_LO,
                               lane, wm, wn);
            }

            // tile B's gz/gh (latency hides under gruA + gemmB issue)
            float2 gzB[4][2], ghB[4][2];
#pragma unroll
            for (int tn = 0; tn < 4; tn++)
#pragma unroll
                for (int h2 = 0; h2 < 2; h2++) {
                    size_t idx = (baseB + rowsl[h2]) * D + cols[tn];
                    gzB[tn][h2] = __half22float2(*(const __half2*)(g_GZ + idx));
                    ghB[tn][h2] = __half22float2(*(const __half2*)(g_GH + idx));
                }

            // GRU for tile A (reads aZ/aH before gemmB overwrites: in-order issue)
#pragma unroll
            for (int tn = 0; tn < 4; tn++)
#pragma unroll
                for (int h2 = 0; h2 < 2; h2++) {
                    float z0 = fsig(gzA[tn][h2].x + aZ[tn][h2 * 2]     + bzv[tn].x);
                    float z1 = fsig(gzA[tn][h2].y + aZ[tn][h2 * 2 + 1] + bzv[tn].y);
                    float c0 = ftanh(ghA[tn][h2].x + aH[tn][h2 * 2]     + bhv[tn].x);
                    float c1 = ftanh(ghA[tn][h2].y + aH[tn][h2 * 2 + 1] + bhv[tn].y);
                    SA[tn][h2 * 2]     = (1.f - z0) * SA[tn][h2 * 2]     + z0 * c0;
                    SA[tn][h2 * 2 + 1] = (1.f - z1) * SA[tn][h2 * 2 + 1] + z1 * c1;
                }

            if (t > 0) {
#pragma unroll
                for (int tn = 0; tn < 4; tn++)
#pragma unroll
                    for (int q = 0; q < 4; q++) { aZ[tn][q] = 0.f; aH[tn][q] = 0.f; }
                gemm_step_dual(aZ, aH, sxBhi, sxBlo,
                               sb + SW0_HI, sb + SW0_LO, sb + SW1_HI, sb + SW1_LO,
                               lane, wm, wn);
            }

            // GRU for tile B
#pragma unroll
            for (int tn = 0; tn < 4; tn++)
#pragma unroll
                for (int h2 = 0; h2 < 2; h2++) {
                    float z0 = fsig(gzB[tn][h2].x + aZ[tn][h2 * 2]     + bzv[tn].x);
                    float z1 = fsig(gzB[tn][h2].y + aZ[tn][h2 * 2 + 1] + bzv[tn].y);
                    float c0 = ftanh(ghB[tn][h2].x + aH[tn][h2 * 2]     + bhv[tn].x);
                    float c1 = ftanh(ghB[tn][h2].y + aH[tn][h2 * 2 + 1] + bhv[tn].y);
                    SB[tn][h2 * 2]     = (1.f - z0) * SB[tn][h2 * 2]     + z0 * c0;
                    SB[tn][h2 * 2 + 1] = (1.f - z1) * SB[tn][h2 * 2 + 1] + z1 * c1;
                }

            if (t > 0 && t + 1 < NT) BARH(barid);  // gemm reads done before next split
        }

        // write final states
#pragma unroll
        for (int tn = 0; tn < 4; tn++)
#pragma unroll
            for (int h2 = 0; h2 < 2; h2++) {
                int growA = tileA * 32 + rowsl[h2];
                *(float2*)(out + (size_t)growA * D + cols[tn]) =
                    make_float2(SA[tn][h2 * 2], SA[tn][h2 * 2 + 1]);
                if (vB) {
                    int growB = tileB * 32 + rowsl[h2];
                    *(float2*)(out + (size_t)growB * D + cols[tn]) =
                        make_float2(SB[tn][h2 * 2], SB[tn][h2 * 2 + 1]);
                }
            }
    }
}

// ---------------------------------------------------------------------------
extern "C" void kernel_launch(void* const* d_in, const int* in_sizes, int n_in,
                              void* d_out, int out_size) {
    const int*   ei       = (const int*)d_in[0];
    const int*   src      = ei;
    const int*   dst      = ei + NE;
    const int*   etype    = (const int*)d_in[1];
    const int*   etime    = (const int*)d_in[2];
    const float* ew       = (const float*)d_in[3];
    const float* node_emb = (const float*)d_in[4];
    const float* rel_emb  = (const float*)d_in[5];
    const float* Wenc     = (const float*)d_in[6];
    const float* Wz       = (const float*)d_in[7];
    const float* Uz       = (const float*)d_in[8];
    const float* Wh       = (const float*)d_in[9];
    const float* Uh       = (const float*)d_in[10];
    const float* bz       = (const float*)d_in[11];
    const float* bh       = (const float*)d_in[12];

    cudaFuncSetAttribute(enc_gates, cudaFuncAttributeMaxDynamicSharedMemorySize, SMEM_ENC);
    cudaFuncSetAttribute(step_all,  cudaFuncAttributeMaxDynamicSharedMemorySize, SMEM_STEP);

    void* aggp = nullptr;
    cudaGetSymbolAddress(&aggp, g_agg);
    cudaMemsetAsync(aggp, 0, (size_t)NT * NRP * D * sizeof(float), 0);

    prep_weights<<<(5 * 128 * 128 + 255) / 256, 256>>>(Wenc, Wz, Uz, Wh, Uh);
    scatter_kernel<<<(NE * 32 + 255) / 256, 256>>>(src, dst, etype, etime, ew,
                                                   node_emb, rel_emb);

    enc_gates<<<148, 512, SMEM_ENC>>>();
    step_all<<<148, 512, SMEM_STEP>>>(bz, bh, (float*)d_out);
}

// round 17
// speedup vs baseline: 1.1663x; 1.1663x over previous
#include <cuda_runtime.h>
#include <cuda_bf16.h>
#include <cuda_fp16.h>
#include <cstdint>

#define NN 20000    // nodes
#define D  128      // dim
#define NE 200000   // edges
#define NT 8        // timesteps
#define NRP 20096   // padded rows (157*128)
#define NTIL64 314  // 64-row tiles (NRP/64)
#define NTT (NT * NTIL64)   // 2512 (t,tile) pairs for enc_gates
#define NTIL32 625  // 32-row tiles for step_all (exact: 625*32 = 20000)
#define PAD 136     // bf16 elems per padded smem row (step_all layout)

// ---- static device scratch (no runtime allocation) ----
__device__ float  g_agg[(size_t)NT * NRP * D];  // per-time aggregated messages
__device__ uint4  g_Wp[5 * 2 * 128 * 16];       // 5 weights x {hi,lo} x [n][k] bf16 linear
__device__ __half g_GZ[(size_t)NT * NRP * D];   // H@Wz (fp16 preact)
__device__ __half g_GH[(size_t)NT * NRP * D];   // H@Wh

// ---- enc_gates smem (XOR-swizzled 256B rows; weight splits are 32KB each) ----
#define EX_HI 0
#define EX_LO 16384
#define EWE_HI 32768
#define EWE_LO 65536
#define EWZ_HI 98304
#define EWZ_LO 131072
#define EWH_HI 163840
#define EWH_LO 196608
#define SMEM_ENC 229376

// ---- step_all smem: Uz + Uh (padded rows) + per-group SX buffers ----
#define SW0_HI 0
#define SW0_LO 34816
#define SW1_HI 69632
#define SW1_LO 104448
#define SXBASE 139264
#define SXG 17408            // per-group SX size (hi 8704 + lo 8704)
#define SMEM_STEP (SXBASE + 2 * SXG)   // 174080

// ---------------------------------------------------------------------------
__device__ __forceinline__ uint32_t smem_u32(const void* p) {
    uint32_t a;
    asm("{ .reg .u64 t; cvta.to.shared.u64 t, %1; cvt.u32.u64 %0, t; }" : "=r"(a) : "l"(p));
    return a;
}

#define LDSM4(R, a) \
    asm volatile("ldmatrix.sync.aligned.m8n8.x4.shared.b16 {%0,%1,%2,%3}, [%4];" \
                 : "=r"((R)[0]), "=r"((R)[1]), "=r"((R)[2]), "=r"((R)[3]) : "r"(a))

#define MMA16816(d, a, b0, b1) \
    asm volatile("mma.sync.aligned.m16n8k16.row.col.f32.bf16.bf16.f32 " \
                 "{%0,%1,%2,%3},{%4,%5,%6,%7},{%8,%9},{%0,%1,%2,%3};" \
                 : "+f"((d)[0]), "+f"((d)[1]), "+f"((d)[2]), "+f"((d)[3]) \
                 : "r"((a)[0]), "r"((a)[1]), "r"((a)[2]), "r"((a)[3]), "r"(b0), "r"(b1))

#define BARH(id) asm volatile("bar.sync %0, 128;" :: "r"(id) : "memory")

__device__ __forceinline__ void split2(float x, float y, uint32_t& h, uint32_t& l) {
    __nv_bfloat16 hx = __float2bfloat16(x), hy = __float2bfloat16(y);
    float rx = x - __bfloat162float(hx);
    float ry = y - __bfloat162float(hy);
    __nv_bfloat16 lx = __float2bfloat16(rx), ly = __float2bfloat16(ry);
    h = (uint32_t)__bfloat16_as_ushort(hx) | ((uint32_t)__bfloat16_as_ushort(hy) << 16);
    l = (uint32_t)__bfloat16_as_ushort(lx) | ((uint32_t)__bfloat16_as_ushort(ly) << 16);
}

// Fast MUFU-based transcendentals (rel err ~1e-6; inf-safe saturation)
__device__ __forceinline__ float fsig(float x) {
    return __fdividef(1.f, 1.f + __expf(-x));
}
__device__ __forceinline__ float ftanh(float x) {
    return 1.f - __fdividef(2.f, __expf(2.f * x) + 1.f);
}

// ---------------------------------------------------------------------------
__global__ void prep_weights(const float* W0, const float* W1, const float* W2,
                             const float* W3, const float* W4) {
    int idx = blockIdx.x * blockDim.x + threadIdx.x;
    if (idx >= 5 * 128 * 128) return;
    int w = idx >> 14, rem = idx & 16383, n = rem >> 7, k = rem & 127;
    const float* Ws = (w == 0) ? W0 : (w == 1) ? W1 : (w == 2) ? W2 : (w == 3) ? W3 : W4;
    float v = Ws[k * 128 + n];
    __nv_bfloat16 hv = __float2bfloat16(v);
    float res = v - __bfloat162float(hv);
    __nv_bfloat16 lv = __float2bfloat16(res);
    unsigned short* base = (unsigned short*)g_Wp;
    base[(size_t)((w * 2 + 0) * 128 + n) * 128 + k] = __bfloat16_as_ushort(hv);
    base[(size_t)((w * 2 + 1) * 128 + n) * 128 + k] = __bfloat16_as_ushort(lv);
}

__global__ void scatter_kernel(const int* __restrict__ src, const int* __restrict__ dst,
                               const int* __restrict__ etype, const int* __restrict__ etime,
                               const float* __restrict__ ew,
                               const float* __restrict__ node_emb,
                               const float* __restrict__ rel_emb) {
    int gid  = blockIdx.x * blockDim.x + threadIdx.x;
    int e    = gid >> 5;
    int lane = gid & 31;
    if (e >= NE) return;
    int t = etime[e];
    if ((unsigned)t >= NT) return;
    int s = src[e], d = dst[e], r = etype[e];
    float w = ew[e];
    float4 a = reinterpret_cast<const float4*>(node_emb + (size_t)s * D)[lane];
    float4 b = reinterpret_cast<const float4*>(rel_emb  + (size_t)r * D)[lane];
    float* o = g_agg + ((size_t)t * NRP + d) * D + lane * 4;
    asm volatile("red.global.add.v4.f32 [%0], {%1,%2,%3,%4};"
                 :: "l"(o), "f"(a.x * b.x * w), "f"(a.y * b.y * w),
                    "f"(a.z * b.z * w), "f"(a.w * b.w * w) : "memory");
}

// ---------------------------------------------------------------------------
// enc_gates: fused H = tanh(agg@Wenc) smem-only, then dual GZ/GH GEMM sharing
// H fragments. 64-row tiles, 512 thr, XOR-swizzle 256B rows. fp16 outputs.
// ---------------------------------------------------------------------------
__device__ __forceinline__ void copy_w_swz(char* sm_, int w, int tid,
                                           int hi_off, int lo_off) {
    const uint4* s = g_Wp + (size_t)w * 4096;
    for (int i = tid; i < 4096; i += 512) {
        int sp = i >> 11, j = i & 2047, n = j >> 4, c = j & 15;
        uint32_t off = (uint32_t)(n * 256) + (((c ^ (n & 7)) & 15) << 4);
        *(uint4*)(sm_ + (sp ? lo_off : hi_off) + off) = s[i];
    }
}

__device__ __forceinline__ void gemm64sw(float (&acc)[2][2][4],
                                         uint32_t xhi, uint32_t xlo,
                                         uint32_t whi, uint32_t wlo,
                                         int lane, int wm, int wn) {
    int ar = wm * 32 + (lane & 15);
    int ach = lane >> 4;
    int brow = wn * 16 + (lane & 7) + ((lane >> 4) & 1) * 8;
    int bch = (lane >> 3) & 1;
    uint32_t ab0 = (uint32_t)(ar * 256), ab1 = (uint32_t)((ar + 16) * 256);
    int am = ar & 7;
    uint32_t bb = (uint32_t)(brow * 256);
    int bm = brow & 7;
#pragma unroll 2
    for (int ks = 0; ks < 8; ks++) {
        uint32_t Ah[2][4], Al[2][4], Bh[4], Bl[4];
        uint32_t ao = (uint32_t)((((ks * 2 + ach) ^ am) & 15) << 4);
        uint32_t bo = (uint32_t)((((ks * 2 + bch) ^ bm) & 15) << 4);
        LDSM4(Ah[0], xhi + ab0 + ao);
        LDSM4(Al[0], xlo + ab0 + ao);
        LDSM4(Ah[1], xhi + ab1 + ao);
        LDSM4(Al[1], xlo + ab1 + ao);
        LDSM4(Bh, whi + bb + bo);
        LDSM4(Bl, wlo + bb + bo);
#pragma unroll
        for (int tm = 0; tm < 2; tm++)
#pragma unroll
            for (int tn = 0; tn < 2; tn++) {
                int o = tn * 2;
                MMA16816(acc[tm][tn], Ah[tm], Bh[o], Bh[o + 1]);
                MMA16816(acc[tm][tn], Al[tm], Bh[o], Bh[o + 1]);
                MMA16816(acc[tm][tn], Ah[tm], Bl[o], Bl[o + 1]);
            }
    }
}

__device__ __forceinline__ void gemm64sw_dual(float (&aZ)[2][2][4], float (&aH)[2][2][4],
                                              uint32_t xhi, uint32_t xlo,
                                              uint32_t zhi, uint32_t zlo,
                                              uint32_t hhi, uint32_t hlo,
                                              int lane, int wm, int wn) {
    int ar = wm * 32 + (lane & 15);
    int ach = lane >> 4;
    int brow = wn * 16 + (lane & 7) + ((lane >> 4) & 1) * 8;
    int bch = (lane >> 3) & 1;
    uint32_t ab0 = (uint32_t)(ar * 256), ab1 = (uint32_t)((ar + 16) * 256);
    int am = ar & 7;
    uint32_t bb = (uint32_t)(brow * 256);
    int bm = brow & 7;
#pragma unroll 2
    for (int ks = 0; ks < 8; ks++) {
        uint32_t Ah[2][4], Al[2][4], Bzh[4], Bzl[4], Bhh[4], Bhl[4];
        uint32_t ao = (uint32_t)((((ks * 2 + ach) ^ am) & 15) << 4);
        uint32_t bo = (uint32_t)((((ks * 2 + bch) ^ bm) & 15) << 4);
        LDSM4(Ah[0], xhi + ab0 + ao);
        LDSM4(Al[0], xlo + ab0 + ao);
        LDSM4(Ah[1], xhi + ab1 + ao);
        LDSM4(Al[1], xlo + ab1 + ao);
        LDSM4(Bzh, zhi + bb + bo);
        LDSM4(Bzl, zlo + bb + bo);
        LDSM4(Bhh, hhi + bb + bo);
        LDSM4(Bhl, hlo + bb + bo);
#pragma unroll
        for (int tm = 0; tm < 2; tm++)
#pragma unroll
            for (int tn = 0; tn < 2; tn++) {
                int o = tn * 2;
                MMA16816(aZ[tm][tn], Ah[tm], Bzh[o], Bzh[o + 1]);
                MMA16816(aZ[tm][tn], Al[tm], Bzh[o], Bzh[o + 1]);
                MMA16816(aZ[tm][tn], Ah[tm], Bzl[o], Bzl[o + 1]);
                MMA16816(aH[tm][tn], Ah[tm], Bhh[o], Bhh[o + 1]);
                MMA16816(aH[tm][tn], Al[tm], Bhh[o], Bhh[o + 1]);
                MMA16816(aH[tm][tn], Ah[tm], Bhl[o], Bhl[o + 1]);
            }
    }
}

#define ZERO_ACC224(acc) \
    { _Pragma("unroll") for (int i = 0; i < 2; i++) \
      _Pragma("unroll") for (int j = 0; j < 2; j++) \
      _Pragma("unroll") for (int q = 0; q < 4; q++) (acc)[i][j][q] = 0.f; }

__global__ void __launch_bounds__(512, 1) enc_gates() {
    extern __shared__ char sm[];
    uint32_t sb = smem_u32(sm);
    int tid = threadIdx.x, lane = tid & 31, wid = tid >> 5;
    int wm = wid & 1, wn = wid >> 1;

    copy_w_swz(sm, 0, tid, EWE_HI, EWE_LO);
    copy_w_swz(sm, 1, tid, EWZ_HI, EWZ_LO);
    copy_w_swz(sm, 3, tid, EWH_HI, EWH_LO);

    int xrow = tid >> 3, xseg = (tid & 7) * 16;
    int xc0 = xseg >> 3;

    float4 pf[4];
    {
        int tt = blockIdx.x;
        int t = tt / NTIL64, tile = tt - t * NTIL64;
        const float4* s = (const float4*)(g_agg + ((size_t)t * NRP + tile * 64 + xrow) * D + xseg);
#pragma unroll
        for (int q = 0; q < 4; q++) pf[q] = s[q];
    }

    for (int tt = blockIdx.x; tt < NTT; tt += gridDim.x) {
        int t = tt / NTIL64, tile = tt - t * NTIL64;

        __syncthreads();
#pragma unroll
        for (int g = 0; g < 2; g++) {
            float4 a = pf[g * 2], b = pf[g * 2 + 1];
            uint32_t h0, h1, h2, h3, l0, l1, l2, l3;
            split2(a.x, a.y, h0, l0);
            split2(a.z, a.w, h1, l1);
            split2(b.x, b.y, h2, l2);
            split2(b.z, b.w, h3, l3);
            uint32_t off = (uint32_t)(xrow * 256) + ((((xc0 + g) ^ (xrow & 7)) & 15) << 4);
            *(uint4*)(sm + EX_HI + off) = make_uint4(h0, h1, h2, h3);
            *(uint4*)(sm + EX_LO + off) = make_uint4(l0, l1, l2, l3);
        }
        __syncthreads();

        float acc[2][2][4];
        ZERO_ACC224(acc);
        gemm64sw(acc, sb + EX_HI, sb + EX_LO, sb + EWE_HI, sb + EWE_LO, lane, wm, wn);
        __syncthreads();

#pragma unroll
        for (int tm = 0; tm < 2; tm++)
#pragma unroll
            for (int tn = 0; tn < 2; tn++) {
                int c = wn * 16 + tn * 8 + (lane & 3) * 2;
#pragma unroll
                for (int h2i = 0; h2i < 2; h2i++) {
                    int r = wm * 32 + tm * 16 + (lane >> 2) + h2i * 8;
                    uint32_t h, l;
                    split2(ftanh(acc[tm][tn][h2i * 2]), ftanh(acc[tm][tn][h2i * 2 + 1]), h, l);
                    uint32_t off = (uint32_t)(r * 256) + ((((c >> 3) ^ (r & 7)) & 15) << 4)
                                 + (uint32_t)((c & 7) * 2);
                    *(uint32_t*)(sm + EX_HI + off) = h;
                    *(uint32_t*)(sm + EX_LO + off) = l;
                }
            }
        __syncthreads();

        if (tt + (int)gridDim.x < NTT) {
            int nt2 = tt + gridDim.x;
            int t2 = nt2 / NTIL64, tile2 = nt2 - t2 * NTIL64;
            const float4* s = (const float4*)(g_agg + ((size_t)t2 * NRP + tile2 * 64 + xrow) * D + xseg);
#pragma unroll
            for (int q = 0; q < 4; q++) pf[q] = s[q];
        }

        float accZ[2][2][4], accH[2][2][4];
        ZERO_ACC224(accZ);
        ZERO_ACC224(accH);
        gemm64sw_dual(accZ, accH, sb + EX_HI, sb + EX_LO,
                      sb + EWZ_HI, sb + EWZ_LO, sb + EWH_HI, sb + EWH_LO, lane, wm, wn);

        size_t base = (size_t)t * NRP + (size_t)tile * 64;
#pragma unroll
        for (int tm = 0; tm < 2; tm++)
#pragma unroll
            for (int tn = 0; tn < 2; tn++) {
                int c = wn * 16 + tn * 8 + (lane & 3) * 2;
#pragma unroll
                for (int h2i = 0; h2i < 2; h2i++) {
                    int r = wm * 32 + tm * 16 + (lane >> 2) + h2i * 8;
                    __half2 hz = __floats2half2_rn(accZ[tm][tn][h2i * 2], accZ[tm][tn][h2i * 2 + 1]);
                    __half2 hh = __floats2half2_rn(accH[tm][tn][h2i * 2], accH[tm][tn][h2i * 2 + 1]);
                    *(__half2*)(g_GZ + (base + r) * D + c) = hz;
                    *(__half2*)(g_GH + (base + r) * D + c) = hh;
                }
            }
    }
}

// ---------------------------------------------------------------------------
// step_all (R14-proven): 2 groups/CTA x 2 wm-halves = 4 sync domains (named
// bar.sync, 128 thr). Group owns a 32-row tile stream; warp tile 16m x 32n.
// State in registers across t; gz/gh loaded as fp16 (early-issued).
// ---------------------------------------------------------------------------
__device__ __forceinline__ void copy_w_pad(char* sm_, int w, int tid,
                                           int hi_off, int lo_off) {
    const uint4* s = g_Wp + (size_t)w * 4096;
    for (int i = tid; i < 4096; i += 512) {
        int sp = i >> 11, j = i & 2047, n = j >> 4, kk = j & 15;
        *(uint4*)(sm_ + (sp ? lo_off : hi_off) + (uint32_t)(n * PAD + kk * 8) * 2) = s[i];
    }
}

__device__ __forceinline__ void gemm_step_dual(float (&aZ)[4][4], float (&aH)[4][4],
                                               uint32_t xhi, uint32_t xlo,
                                               uint32_t zhi, uint32_t zlo,
                                               uint32_t hhi, uint32_t hlo,
                                               int lane, int wm, int wn) {
    const int arow = wm * 16 + (lane & 15);
    const int acolo = (lane >> 4) * 8;
    const int brow = wn * 32 + (lane & 7) + ((lane >> 4) & 1) * 8;
    const int bcolo = ((lane >> 3) & 1) * 8;
    const uint32_t bstep = (uint32_t)(16 * PAD) * 2;
#pragma unroll 1
    for (int ks = 0; ks < 8; ks++) {
        uint32_t Ah[4], Al[4], Bzh[8], Bzl[8], Bhh[8], Bhl[8];
        uint32_t ao = (uint32_t)(arow * PAD + ks * 16 + acolo) * 2;
        uint32_t bo = (uint32_t)(brow * PAD + ks * 16 + bcolo) * 2;
        LDSM4(Ah, xhi + ao);
        LDSM4(Al, xlo + ao);
        LDSM4(Bzh, zhi + bo);
        LDSM4(Bzh + 4, zhi + bo + bstep);
        LDSM4(Bzl, zlo + bo);
        LDSM4(Bzl + 4, zlo + bo + bstep);
        LDSM4(Bhh, hhi + bo);
        LDSM4(Bhh + 4, hhi + bo + bstep);
        LDSM4(Bhl, hlo + bo);
        LDSM4(Bhl + 4, hlo + bo + bstep);
#pragma unroll
        for (int tn = 0; tn < 4; tn++) {
            int o = tn * 2;
            MMA16816(aZ[tn], Ah, Bzh[o], Bzh[o + 1]);
            MMA16816(aZ[tn], Al, Bzh[o], Bzh[o + 1]);
            MMA16816(aZ[tn], Ah, Bzl[o], Bzl[o + 1]);
            MMA16816(aH[tn], Ah, Bhh[o], Bhh[o + 1]);
            MMA16816(aH[tn], Al, Bhh[o], Bhh[o + 1]);
            MMA16816(aH[tn], Ah, Bhl[o], Bhl[o + 1]);
        }
    }
}

__global__ void __launch_bounds__(512, 1) step_all(const float* __restrict__ bz,
                                                   const float* __restrict__ bh,
                                                   float* __restrict__ out) {
    extern __shared__ char sm[];
    uint32_t sb = smem_u32(sm);
    int tid = threadIdx.x, lane = tid & 31, wid = tid >> 5;
    int grp = wid >> 3;
    int lw = wid & 7;
    int wm = lw & 1, wn = lw >> 1;
    int barid = 1 + grp * 2 + wm;

    copy_w_pad(sm, 2, tid, SW0_HI, SW0_LO);  // Uz
    copy_w_pad(sm, 4, tid, SW1_HI, SW1_LO);  // Uh

    uint32_t sxhi = sb + SXBASE + grp * SXG;
    uint32_t sxlo = sxhi + 8704;

    int cols[4];
#pragma unroll
    for (int tn = 0; tn < 4; tn++) cols[tn] = wn * 32 + tn * 8 + (lane & 3) * 2;
    int rowsl[2];
#pragma unroll
    for (int h2 = 0; h2 < 2; h2++) rowsl[h2] = wm * 16 + (lane >> 2) + h2 * 8;

    float2 bzv[4], bhv[4];
#pragma unroll
    for (int tn = 0; tn < 4; tn++) {
        bzv[tn] = *(const float2*)(bz + cols[tn]);
        bhv[tn] = *(const float2*)(bh + cols[tn]);
    }
    __syncthreads();  // weights ready (only full-CTA barrier)

    for (int tile = blockIdx.x * 2 + grp; tile < NTIL32; tile += 296) {
        float S[4][4];
#pragma unroll
        for (int tn = 0; tn < 4; tn++)
#pragma unroll
            for (int q = 0; q < 4; q++) S[tn][q] = 0.f;

        for (int t = 0; t < NT; t++) {
            size_t base = (size_t)t * NRP + (size_t)tile * 32;
            float2 gz[4][2], gh[4][2];
#pragma unroll
            for (int tn = 0; tn < 4; tn++)
#pragma unroll
                for (int h2 = 0; h2 < 2; h2++) {
                    size_t idx = (base + rowsl[h2]) * D + cols[tn];
                    gz[tn][h2] = __half22float2(*(const __half2*)(g_GZ + idx));
                    gh[tn][h2] = __half22float2(*(const __half2*)(g_GH + idx));
                }

            float aZ[4][4], aH[4][4];
#pragma unroll
            for (int tn = 0; tn < 4; tn++)
#pragma unroll
                for (int q = 0; q < 4; q++) { aZ[tn][q] = 0.f; aH[tn][q] = 0.f; }

            if (t > 0) {
#pragma unroll
                for (int tn = 0; tn < 4; tn++)
#pragma unroll
                    for (int h2 = 0; h2 < 2; h2++) {
                        uint32_t h, l;
                        split2(S[tn][h2 * 2], S[tn][h2 * 2 + 1], h, l);
                        uint32_t off = (uint32_t)(rowsl[h2] * PAD + cols[tn]) * 2;
                        *(uint32_t*)(sm + SXBASE + grp * SXG + off) = h;
                        *(uint32_t*)(sm + SXBASE + grp * SXG + 8704 + off) = l;
                    }
                BARH(barid);
                gemm_step_dual(aZ, aH, sxhi, sxlo,
                               sb + SW0_HI, sb + SW0_LO, sb + SW1_HI, sb + SW1_LO,
                               lane, wm, wn);
            }

#pragma unroll
            for (int tn = 0; tn < 4; tn++)
#pragma unroll
                for (int h2 = 0; h2 < 2; h2++) {
                    float z0 = fsig(gz[tn][h2].x + aZ[tn][h2 * 2]     + bzv[tn].x);
                    float z1 = fsig(gz[tn][h2].y + aZ[tn][h2 * 2 + 1] + bzv[tn].y);
                    float c0 = ftanh(gh[tn][h2].x + aH[tn][h2 * 2]     + bhv[tn].x);
                    float c1 = ftanh(gh[tn][h2].y + aH[tn][h2 * 2 + 1] + bhv[tn].y);
                    S[tn][h2 * 2]     = (1.f - z0) * S[tn][h2 * 2]     + z0 * c0;
                    S[tn][h2 * 2 + 1] = (1.f - z1) * S[tn][h2 * 2 + 1] + z1 * c1;
                }
            if (t > 0 && t + 1 < NT) BARH(barid);
        }

#pragma unroll
        for (int tn = 0; tn < 4; tn++)
#pragma unroll
            for (int h2 = 0; h2 < 2; h2++) {
                int grow = tile * 32 + rowsl[h2];
                *(float2*)(out + (size_t)grow * D + cols[tn]) =
                    make_float2(S[tn][h2 * 2], S[tn][h2 * 2 + 1]);
            }
    }
}

// ---------------------------------------------------------------------------
extern "C" void kernel_launch(void* const* d_in, const int* in_sizes, int n_in,
                              void* d_out, int out_size) {
    const int*   ei       = (const int*)d_in[0];
    const int*   src      = ei;
    const int*   dst      = ei + NE;
    const int*   etype    = (const int*)d_in[1];
    const int*   etime    = (const int*)d_in[2];
    const float* ew       = (const float*)d_in[3];
    const float* node_emb = (const float*)d_in[4];
    const float* rel_emb  = (const float*)d_in[5];
    const float* Wenc     = (const float*)d_in[6];
    const float* Wz       = (const float*)d_in[7];
    const float* Uz       = (const float*)d_in[8];
    const float* Wh       = (const float*)d_in[9];
    const float* Uh       = (const float*)d_in[10];
    const float* bz       = (const float*)d_in[11];
    const float* bh       = (const float*)d_in[12];

    cudaFuncSetAttribute(enc_gates, cudaFuncAttributeMaxDynamicSharedMemorySize, SMEM_ENC);
    cudaFuncSetAttribute(step_all,  cudaFuncAttributeMaxDynamicSharedMemorySize, SMEM_STEP);

    void* aggp = nullptr;
    cudaGetSymbolAddress(&aggp, g_agg);
    cudaMemsetAsync(aggp, 0, (size_t)NT * NRP * D * sizeof(float), 0);

    prep_weights<<<(5 * 128 * 128 + 255) / 256, 256>>>(Wenc, Wz, Uz, Wh, Uh);
    scatter_kernel<<<(NE * 32 + 255) / 256, 256>>>(src, dst, etype, etime, ew,
                                                   node_emb, rel_emb);

    enc_gates<<<148, 512, SMEM_ENC>>>();
    step_all<<<148, 512, SMEM_STEP>>>(bz, bh, (float*)d_out);
}